// round 7
// baseline (speedup 1.0000x reference)
#include <cuda_runtime.h>

// Exact integer reformulation of the PUMA crossbar MVM conv (validated R1-R6):
//   out = RNE_clip( conv_int(xi16, dw) / 4096 ) / 4096
//   xi16 = sext16(rint(x*4096)),  dw = clamp(rint(w*4096), +/-65535)
//
// R7: single launch (quantize into SMEM on the fly). Column-sliding mainloop
// with 2 ow-columns per thread (LDS.64 x-loads) -> 72 IMAD per ci per thread
// (86% IMAD issue density). Grid 512 x 128 threads: co-chunk 8, oh-pair,
// 4-way ci-split where quarter == warp, shuffle combine intra-warp (width 8),
// int SMEM reduction. ~3.5 warps/SMSP resident.

namespace {
constexpr int CIN = 64, H = 16, W = 16, COUT = 128;
constexpr int L = CIN * 9;        // 576
constexpr int CO_CHUNK = 8;
constexpr int THREADS = 128;      // 8 owpair x 2 cog(4co) x 2 ohsub x 4 ci-quarter
}

__device__ __forceinline__ float rne_fix(int S) {
    int base = S >> 12;                 // floor(S/4096)
    int rem  = S - (base << 12);        // 0..4095
    if (rem > 2048)       base += 1;
    else if (rem == 2048) base += (base & 1);   // ties to even
    base = max(-32768, min(32767, base));
    return (float)base * (1.0f / 4096.0f);
}

__global__ __launch_bounds__(THREADS, 3)
void conv_mvm_kernel(const float* __restrict__ x,
                     const float* __restrict__ w,
                     float* __restrict__ out)
{
    __shared__ int sw[L * CO_CHUNK];   // 18432 B : [l][co_local(8)]
    __shared__ int sx[CIN * 4 * 16];   // 16384 B : [ci][r 0..3][col 0..15] sign-extended
    __shared__ int red[3][32][8];      //  3072 B : quarters 1..3 partials

    const int bid     = blockIdx.x;       // 512 = 16 chunks x 8 ohp x 4 b
    const int coChunk = bid & 15;
    const int ohp     = (bid >> 4) & 7;
    const int b       = bid >> 7;

    const int tid     = threadIdx.x;
    const int p       = tid & 7;          // ow pair -> cols 2p, 2p+1
    const int cog     = (tid >> 3) & 1;   // group of 4 Cout
    const int ohsub   = (tid >> 4) & 1;
    const int quarter = tid >> 5;         // == warp id; ci quarter

    // ---- stage weights: quantize on the fly, tile layout [l][co] ----
    {
        const float* wsrc = w + coChunk * CO_CHUNK * L;
        #pragma unroll
        for (int it = 0; it < (CO_CHUNK * L) / THREADS; ++it) {
            int idx = it * THREADS + tid;
            int co  = idx / L;
            int l   = idx - co * L;
            int q = __float2int_rn(wsrc[idx] * 4096.0f);
            q = max(-65535, min(65535, q));
            sw[l * CO_CHUNK + co] = q;
        }
    }

    // ---- stage inputs: 4 rows x 16 cols x 64 ci, quantize + sext16 ----
    #pragma unroll
    for (int it = 0; it < (CIN * 4 * 16) / THREADS; ++it) {
        int idx = it * THREADS + tid;
        int col = idx & 15;
        int r   = (idx >> 4) & 3;
        int ci  = idx >> 6;
        int gr  = ohp * 2 - 1 + r;
        int v = 0;
        if ((unsigned)gr < (unsigned)H) {
            int xi = __float2int_rn(x[((b * CIN + ci) * H + gr) * W + col] * 4096.0f);
            v = (xi << 16) >> 16;          // 16-bit two's complement wrap
        }
        sx[idx] = v;
    }
    __syncthreads();

    // ---- mainloop: 16 ci x (3 LDS.64 x + 9 LDS.128 w + 72 IMAD) ----
    // A[c][kj][m]: partial sums for column c (2p+c), col-tap kj, cout m.
    int A[2][3][4] = {};
    const int ciBase = quarter * (CIN / 4);
    #pragma unroll 4
    for (int i = 0; i < CIN / 4; ++i) {
        const int ci = ciBase + i;
        const int* xp = &sx[(ci * 4 + ohsub) * 16 + p * 2];
        const int* wp = &sw[ci * 9 * CO_CHUNK + cog * 4];
        #pragma unroll
        for (int ki = 0; ki < 3; ++ki) {
            int2 xv = *(const int2*)&xp[ki * 16];    // x[row][2p], x[row][2p+1]
            #pragma unroll
            for (int kj = 0; kj < 3; ++kj) {
                int4 wv = *(const int4*)&wp[(ki * 3 + kj) * CO_CHUNK];
                A[0][kj][0] += xv.x * wv.x;  A[0][kj][1] += xv.x * wv.y;
                A[0][kj][2] += xv.x * wv.z;  A[0][kj][3] += xv.x * wv.w;
                A[1][kj][0] += xv.y * wv.x;  A[1][kj][1] += xv.y * wv.y;
                A[1][kj][2] += xv.y * wv.z;  A[1][kj][3] += xv.y * wv.w;
            }
        }
    }

    // ---- sliding-window combine across lanes (width 8 == p dimension) ----
    // out[2p]   = A[1][0](p-1) + A[0][1] + A[1][2]
    // out[2p+1] = A[0][0]      + A[1][1] + A[0][2](p+1)
    // boundary columns are pad==0, so edge terms are zeroed exactly.
    const unsigned m32 = 0xFFFFFFFFu;
    int s0[4], s1[4];
    #pragma unroll
    for (int m = 0; m < 4; ++m) {
        int up = __shfl_up_sync(m32, A[1][0][m], 1, 8);
        int dn = __shfl_down_sync(m32, A[0][2][m], 1, 8);
        if (p == 0) up = 0;
        if (p == 7) dn = 0;
        s0[m] = up + A[0][1][m] + A[1][2][m];
        s1[m] = A[0][0][m] + A[1][1][m] + dn;
    }

    // ---- reduce ci-quarters via SMEM (quarter == warp) ----
    if (quarter != 0) {
        int lane = tid & 31;
        #pragma unroll
        for (int m = 0; m < 4; ++m) {
            red[quarter - 1][lane][m]     = s0[m];
            red[quarter - 1][lane][4 + m] = s1[m];
        }
    }
    __syncthreads();
    if (quarter != 0) return;

    #pragma unroll
    for (int q = 0; q < 3; ++q)
        #pragma unroll
        for (int m = 0; m < 4; ++m) {
            s0[m] += red[q][tid][m];
            s1[m] += red[q][tid][4 + m];
        }

    // ---- epilogue: RNE to 1/4096 grid, clip int16, STG.64 ----
    const int oh    = ohp * 2 + ohsub;
    const int coOut = coChunk * CO_CHUNK + cog * 4;
    const int ow0   = p * 2;
    #pragma unroll
    for (int m = 0; m < 4; ++m) {
        float2 o;
        o.x = rne_fix(s0[m]);
        o.y = rne_fix(s1[m]);
        *(float2*)&out[((b * COUT + coOut + m) * H + oh) * W + ow0] = o;
    }
}

extern "C" void kernel_launch(void* const* d_in, const int* in_sizes, int n_in,
                              void* d_out, int out_size) {
    const float* x = (const float*)d_in[0];
    const float* w = (const float*)d_in[1];
    // defensive: identify tensors by element count (x: 65536, w: 73728)
    if (n_in >= 2 && in_sizes[0] == 73728 && in_sizes[1] == 65536) {
        x = (const float*)d_in[1];
        w = (const float*)d_in[0];
    }
    conv_mvm_kernel<<<512, THREADS>>>(x, w, (float*)d_out);
}